// round 12
// baseline (speedup 1.0000x reference)
#include <cuda_runtime.h>
#include <cuda_bf16.h>

// ---------------------------------------------------------------------------
// Weight_Generation: conv3x3(3->16) + BatchNorm(train) + ReLU on [1024,3,32,32]
// plus hypernetwork generating 36 conv weight tensors from 242 z-vectors.
// Output layout (float32): [ 36 weight tensors = 242*2304 floats ][ y ]
//
// Schedule (graph, fork/join):
//   main:  prep -> memcpyToSymbol(c_wb) -> conv(2048) -> [join] -> norm
//   side:  hyper(242)   (independent of c_wb; overlaps the prefix + conv head)
// ---------------------------------------------------------------------------

#define Y_OFFSET   (242 * 2304)
#define N_ELEM_PER_CH (1024.0f * 1024.0f)
#define N_CONV_BLOCKS 2048               // 2 blocks per image (16 rows each)

typedef unsigned long long ull;

__device__ float g_partials[N_CONV_BLOCKS * 32];
__device__ float g_scale[16];
__device__ float g_shift[16];
__device__ ull   g_stage[224];
__device__ int   g_count = 0;

// conv weight pairs (216) + bias pairs (8)
__constant__ ull c_wb[224];

__constant__ int c_offs[37] = {
    0,1,2,3,4,5,6,7,8,9,10,11,12,
    14,
    18,22,26,30,34,38,42,46,50,54,58,
    66,
    82,98,114,130,146,162,178,194,210,226,242
};
__constant__ int c_in[36] = {
    1,1,1,1,1,1,1,1,1,1,1,1,
    1,
    2,2,2,2,2,2,2,2,2,2,2,
    2,
    4,4,4,4,4,4,4,4,4,4,4
};

// ---- packed f32x2 helpers --------------------------------------------------
__device__ __forceinline__ ull pack2(float lo, float hi) {
    ull r; asm("mov.b64 %0, {%1, %2};" : "=l"(r) : "f"(lo), "f"(hi)); return r;
}
__device__ __forceinline__ void unpack2(ull v, float& lo, float& hi) {
    asm("mov.b64 {%0, %1}, %2;" : "=f"(lo), "=f"(hi) : "l"(v));
}
__device__ __forceinline__ ull fma2(ull a, ull b, ull c) {
    ull d; asm("fma.rn.f32x2 %0, %1, %2, %3;" : "=l"(d) : "l"(a), "l"(b), "l"(c)); return d;
}
__device__ __forceinline__ ull add2(ull a, ull b) {
    ull d; asm("add.rn.f32x2 %0, %1, %2;" : "=l"(d) : "l"(a), "l"(b)); return d;
}

// ---------------------------------------------------------------------------
__global__ void prep_kernel(const float* __restrict__ cw, const float* __restrict__ cb)
{
    int t = threadIdx.x;
    if (t < 216) {
        int it = t >> 3, j = t & 7;
        int c = it / 9, r9 = it % 9, ky = r9 / 3, kx = r9 % 3;
        int o0 = 2 * j;
        g_stage[t] = pack2(cw[((o0 * 3 + c) * 3 + ky) * 3 + kx],
                           cw[(((o0 + 1) * 3 + c) * 3 + ky) * 3 + kx]);
    } else if (t < 224) {
        int j = t - 216;
        g_stage[t] = pack2(cb[2 * j], cb[2 * j + 1]);
    }
}

// ---------------------------------------------------------------------------
// conv kernel (2048 blocks). Last block reduces partials -> g_scale/g_shift.
// ---------------------------------------------------------------------------
#define SP2_CH   612                      // 18*34 ull per channel
#define SMEM_ULL (3*SP2_CH + 512 + 1)     // + red2 (1024 f) + is_last flag

__global__ __launch_bounds__(256, 5) void conv_kernel(
    const float* __restrict__ x, float* __restrict__ y,
    const float* __restrict__ bn_gamma, const float* __restrict__ bn_beta)
{
    __shared__ __align__(16) ull smem_raw[SMEM_ULL];
    const int tid = threadIdx.x;

    ull*   sp2  = smem_raw;                        // 3*612
    float* red2 = (float*)(smem_raw + 3 * SP2_CH); // 1024 floats
    int*   flag = (int*)(smem_raw + 3 * SP2_CH + 512);

    const int n  = blockIdx.x >> 1;
    const int h0 = (blockIdx.x & 1) << 4;          // 0 or 16
    const float* xi = x + (long)n * 3072;

    // duplicated padded tile: rows h0-1..h0+16, padded cols 0..33
    for (int i = tid; i < 3 * SP2_CH; i += 256) {
        int c = i / SP2_CH, r = i % SP2_CH;
        int yy = r / 34, xx = r % 34;
        int gy = h0 + yy - 1;
        float v = 0.0f;
        if (gy >= 0 && gy < 32 && xx >= 1 && xx < 33)
            v = xi[c * 1024 + gy * 32 + (xx - 1)];
        sp2[i] = pack2(v, v);
    }
    __syncthreads();

    // thread -> row lr (0..15), horizontally adjacent column pair
    const int lr = tid >> 4;
    const int pc0 = (tid & 15) * 2;

    ull acc0[8], acc1[8];
    #pragma unroll
    for (int j = 0; j < 8; j++) { acc0[j] = c_wb[216 + j]; acc1[j] = c_wb[216 + j]; }

    #pragma unroll
    for (int c = 0; c < 3; c++) {
        #pragma unroll
        for (int ky = 0; ky < 3; ky++) {
            const ull* rowp = sp2 + c * SP2_CH + (lr + ky) * 34 + pc0;
            ull v0, v1, v2, v3;
            {
                ulonglong2 t0 = *reinterpret_cast<const ulonglong2*>(rowp);
                ulonglong2 t1 = *reinterpret_cast<const ulonglong2*>(rowp + 2);
                v0 = t0.x; v1 = t0.y; v2 = t1.x; v3 = t1.y;
            }
            #pragma unroll
            for (int kx = 0; kx < 3; kx++) {
                const ull a = (kx == 0) ? v0 : (kx == 1) ? v1 : v2;
                const ull b = (kx == 0) ? v1 : (kx == 1) ? v2 : v3;
                const int tap = (c * 9 + ky * 3 + kx) * 8;
                #pragma unroll
                for (int j = 0; j < 8; j++) {
                    const ull w = c_wb[tap + j];
                    acc0[j] = fma2(a, w, acc0[j]);
                    acc1[j] = fma2(b, w, acc1[j]);
                }
            }
        }
    }

    // epilogue: paired stores + packed stats
    float* yout = y + (long)n * 16 * 1024;
    const int pg = (h0 + lr) * 32 + pc0;
    ull sum2[8], sq2[8];
    #pragma unroll
    for (int j = 0; j < 8; j++) {
        float a0, a1, b0, b1v;
        unpack2(acc0[j], a0, a1);
        unpack2(acc1[j], b0, b1v);
        *reinterpret_cast<float2*>(yout + (2 * j) * 1024 + pg)     = make_float2(a0, b0);
        *reinterpret_cast<float2*>(yout + (2 * j + 1) * 1024 + pg) = make_float2(a1, b1v);
        sum2[j] = add2(acc0[j], acc1[j]);
        sq2[j]  = fma2(acc1[j], acc1[j], fma2(acc0[j], acc0[j], pack2(0.0f, 0.0f)));
    }

    float s[16], q[16];
    #pragma unroll
    for (int j = 0; j < 8; j++) {
        unpack2(sum2[j], s[2 * j], s[2 * j + 1]);
        unpack2(sq2[j],  q[2 * j], q[2 * j + 1]);
    }
    #pragma unroll
    for (int o = 0; o < 16; o++) {
        #pragma unroll
        for (int sft = 16; sft >= 4; sft >>= 1) {
            s[o] += __shfl_down_sync(0xffffffffu, s[o], sft);
            q[o] += __shfl_down_sync(0xffffffffu, q[o], sft);
        }
    }
    const int lane = tid & 31, wp = tid >> 5;
    if (lane < 4) {
        float* rr = red2 + (wp * 4 + lane) * 32;
        #pragma unroll
        for (int o = 0; o < 16; o++) { rr[o] = s[o]; rr[16 + o] = q[o]; }
    }
    __syncthreads();
    if (tid < 32) {
        float t = 0.0f;
        #pragma unroll
        for (int g = 0; g < 32; g++) t += red2[g * 32 + tid];
        g_partials[blockIdx.x * 32 + tid] = t;
    }
    __syncthreads();

    // ---- last-block global stats reduction (R7 version) ----
    if (tid == 0) {
        __threadfence();
        int old = atomicAdd(&g_count, 1);
        *flag = (old == N_CONV_BLOCKS - 1) ? 1 : 0;
    }
    __syncthreads();
    if (*flag) {
        __threadfence();
        const int v = tid & 31, g = tid >> 5;      // 8 groups x 256 blocks
        float t = 0.0f;
        #pragma unroll 8
        for (int b = g * 256; b < (g + 1) * 256; b++)
            t += g_partials[b * 32 + v];
        red2[g * 32 + v] = t;
        __syncthreads();
        if (tid < 32) {
            float tot = 0.0f;
            #pragma unroll
            for (int w = 0; w < 8; w++) tot += red2[w * 32 + tid];
            red2[256 + tid] = tot;
        }
        __syncthreads();
        if (tid < 16) {
            const float inv_n = 1.0f / N_ELEM_PER_CH;
            float mean = red2[256 + tid] * inv_n;
            float var  = red2[256 + 16 + tid] * inv_n - mean * mean;
            float rstd = rsqrtf(var + 1e-5f);
            float sc   = bn_gamma[tid] * rstd;
            g_scale[tid] = sc;
            g_shift[tid] = bn_beta[tid] - mean * sc;
        }
        if (tid == 0) g_count = 0;
    }
}

// ---------------------------------------------------------------------------
// hypernet kernel (242 blocks, side stream)
// ---------------------------------------------------------------------------
__global__ __launch_bounds__(256) void hyper_kernel(
    const float* __restrict__ z_all,
    const float* __restrict__ w1, const float* __restrict__ b1,
    const float* __restrict__ w2, const float* __restrict__ b2,
    float* __restrict__ out)
{
    __shared__ float zs[64];
    __shared__ float hs[1024];
    const int n = blockIdx.x, tid = threadIdx.x;

    if (tid < 64) zs[tid] = z_all[n * 64 + tid];
    __syncthreads();

    for (int e = tid; e < 1024; e += 256) {
        float a = b2[e];
        #pragma unroll 16
        for (int k = 0; k < 64; k++)
            a += zs[k] * w2[k * 1024 + e];
        hs[e] = a;
    }
    __syncthreads();

    int li = 0;
    while (c_offs[li + 1] <= n) li++;
    const int r   = n - c_offs[li];
    const int inn = c_in[li];
    const int o   = r / inn;
    const int ii  = r % inn;
    const long base   = (long)c_offs[li] * 2304 + (long)o * inn * 2304 + (long)ii * 144;
    const int  stride = inn * 144;

    const int oo = tid >> 4;
    const int cbase = (tid & 15) * 9;
    float acc[9];
    #pragma unroll
    for (int j = 0; j < 9; j++) acc[j] = b1[cbase + j];
    #pragma unroll 8
    for (int d = 0; d < 64; d++) {
        float hv = hs[oo * 64 + d];
        const float* w1r = w1 + d * 144 + cbase;
        #pragma unroll
        for (int j = 0; j < 9; j++) acc[j] += hv * w1r[j];
    }
    float* op = out + base + (long)oo * stride + cbase;
    #pragma unroll
    for (int j = 0; j < 9; j++) op[j] = acc[j];
}

// ---------------------------------------------------------------------------
__global__ __launch_bounds__(256) void norm_kernel(float* __restrict__ y)
{
    __shared__ float sc[16], sh[16];
    if (threadIdx.x < 16) {
        sc[threadIdx.x] = g_scale[threadIdx.x];
        sh[threadIdx.x] = g_shift[threadIdx.x];
    }
    __syncthreads();
    const long half = (long)16 * 1024 * 1024 / 8;
    long i0 = (long)blockIdx.x * blockDim.x + threadIdx.x;
    long i1 = i0 + half;
    float4* yv = reinterpret_cast<float4*>(y);

    float4 v0 = yv[i0];
    float4 v1 = yv[i1];
    int cA = (int)((i0 >> 8) & 15);
    int cB = (int)((i1 >> 8) & 15);
    float s0 = sc[cA], b0 = sh[cA];
    float s1 = sc[cB], b1v = sh[cB];
    v0.x = fmaxf(v0.x * s0 + b0, 0.0f);
    v0.y = fmaxf(v0.y * s0 + b0, 0.0f);
    v0.z = fmaxf(v0.z * s0 + b0, 0.0f);
    v0.w = fmaxf(v0.w * s0 + b0, 0.0f);
    v1.x = fmaxf(v1.x * s1 + b1v, 0.0f);
    v1.y = fmaxf(v1.y * s1 + b1v, 0.0f);
    v1.z = fmaxf(v1.z * s1 + b1v, 0.0f);
    v1.w = fmaxf(v1.w * s1 + b1v, 0.0f);
    yv[i0] = v0;
    yv[i1] = v1;
}

// ---------------------------------------------------------------------------
extern "C" void kernel_launch(void* const* d_in, const int* in_sizes, int n_in,
                              void* d_out, int out_size)
{
    const float* x        = (const float*)d_in[0];
    const float* conv_w   = (const float*)d_in[1];
    const float* conv_b   = (const float*)d_in[2];
    const float* bn_gamma = (const float*)d_in[3];
    const float* bn_beta  = (const float*)d_in[4];
    const float* z_all    = (const float*)d_in[5];
    const float* w1       = (const float*)d_in[6];
    const float* b1       = (const float*)d_in[7];
    const float* w2       = (const float*)d_in[8];
    const float* b2       = (const float*)d_in[9];

    float* out = (float*)d_out;
    float* y   = out + Y_OFFSET;

    // one-time resources (created on the uncaptured correctness call)
    static cudaStream_t s1 = nullptr;
    static cudaEvent_t evF = nullptr, evJ = nullptr;
    if (s1 == nullptr) {
        cudaStreamCreateWithFlags(&s1, cudaStreamNonBlocking);
        cudaEventCreateWithFlags(&evF, cudaEventDisableTiming);
        cudaEventCreateWithFlags(&evJ, cudaEventDisableTiming);
    }

    // fork: hypernet on side stream (independent of c_wb)
    cudaEventRecord(evF, 0);
    cudaStreamWaitEvent(s1, evF, 0);
    hyper_kernel<<<242, 256, 0, s1>>>(z_all, w1, b1, w2, b2, out);
    cudaEventRecord(evJ, s1);

    // main stream: weight prep -> constant upload -> conv
    prep_kernel<<<1, 224>>>(conv_w, conv_b);
    void* stage_addr = nullptr;
    cudaGetSymbolAddress(&stage_addr, g_stage);
    cudaMemcpyToSymbolAsync(c_wb, stage_addr, 224 * sizeof(ull), 0,
                            cudaMemcpyDeviceToDevice, 0);
    conv_kernel<<<N_CONV_BLOCKS, 256>>>(x, y, bn_gamma, bn_beta);

    // join side stream, then normalize
    cudaStreamWaitEvent(0, evJ, 0);
    norm_kernel<<<8192, 256>>>(y);
}

// round 13
// speedup vs baseline: 1.1280x; 1.1280x over previous
#include <cuda_runtime.h>
#include <cuda_bf16.h>

// ---------------------------------------------------------------------------
// Weight_Generation: conv3x3(3->16) + BatchNorm(train) + ReLU on [1024,3,32,32]
// plus hypernetwork generating 36 conv weight tensors from 242 z-vectors.
// Output layout (float32): [ 36 weight tensors = 242*2304 floats ][ y ]
// ---------------------------------------------------------------------------

#define Y_OFFSET   (242 * 2304)
#define N_ELEM_PER_CH (1024.0f * 1024.0f)
#define N_CONV_BLOCKS 2048               // 2 blocks per image (16 rows each)

typedef unsigned long long ull;

__device__ float g_partials[N_CONV_BLOCKS * 32];
__device__ float g_scale[16];
__device__ float g_shift[16];
__device__ ull   g_stage[224];           // staging for constant upload
__device__ int   g_count = 0;

// conv weight pairs (216) + bias pairs (8)
__constant__ ull c_wb[224];

__constant__ int c_offs[37] = {
    0,1,2,3,4,5,6,7,8,9,10,11,12,
    14,
    18,22,26,30,34,38,42,46,50,54,58,
    66,
    82,98,114,130,146,162,178,194,210,226,242
};
__constant__ int c_in[36] = {
    1,1,1,1,1,1,1,1,1,1,1,1,
    1,
    2,2,2,2,2,2,2,2,2,2,2,
    2,
    4,4,4,4,4,4,4,4,4,4,4
};

// ---- packed f32x2 helpers --------------------------------------------------
__device__ __forceinline__ ull pack2(float lo, float hi) {
    ull r; asm("mov.b64 %0, {%1, %2};" : "=l"(r) : "f"(lo), "f"(hi)); return r;
}
__device__ __forceinline__ void unpack2(ull v, float& lo, float& hi) {
    asm("mov.b64 {%0, %1}, %2;" : "=f"(lo), "=f"(hi) : "l"(v));
}
__device__ __forceinline__ ull fma2(ull a, ull b, ull c) {
    ull d; asm("fma.rn.f32x2 %0, %1, %2, %3;" : "=l"(d) : "l"(a), "l"(b), "l"(c)); return d;
}
__device__ __forceinline__ ull add2(ull a, ull b) {
    ull d; asm("add.rn.f32x2 %0, %1, %2;" : "=l"(d) : "l"(a), "l"(b)); return d;
}

// ---------------------------------------------------------------------------
__global__ void prep_kernel(const float* __restrict__ cw, const float* __restrict__ cb)
{
    int t = threadIdx.x;
    if (t < 216) {
        int it = t >> 3, j = t & 7;
        int c = it / 9, r9 = it % 9, ky = r9 / 3, kx = r9 % 3;
        int o0 = 2 * j;
        g_stage[t] = pack2(cw[((o0 * 3 + c) * 3 + ky) * 3 + kx],
                           cw[(((o0 + 1) * 3 + c) * 3 + ky) * 3 + kx]);
    } else if (t < 224) {
        int j = t - 216;
        g_stage[t] = pack2(cb[2 * j], cb[2 * j + 1]);
    }
}

// ---------------------------------------------------------------------------
// Fused kernel: blocks [0,2048) = conv half-image tiles; [2048,2290) = hypernet.
// Last conv block reduces all partials -> g_scale/g_shift (no stats launch).
// ---------------------------------------------------------------------------
#define SP2_CH   612                      // 18*34 ull per channel
#define SMEM_ULL (3*SP2_CH + 512 + 1)     // + red2 (1024 f) + is_last flag

__global__ __launch_bounds__(256, 5) void fused_conv_hyper(
    const float* __restrict__ x, float* __restrict__ y,
    const float* __restrict__ bn_gamma, const float* __restrict__ bn_beta,
    const float* __restrict__ z_all,
    const float* __restrict__ w1, const float* __restrict__ b1,
    const float* __restrict__ w2, const float* __restrict__ b2,
    float* __restrict__ out)
{
    __shared__ __align__(16) ull smem_raw[SMEM_ULL];
    const int tid = threadIdx.x;

    if (blockIdx.x < N_CONV_BLOCKS) {
        // ================= CONV PATH =================
        ull*   sp2  = smem_raw;                        // 3*612
        float* red2 = (float*)(smem_raw + 3 * SP2_CH); // 1024 floats
        int*   flag = (int*)(smem_raw + 3 * SP2_CH + 512);

        const int n  = blockIdx.x >> 1;
        const int h0 = (blockIdx.x & 1) << 4;          // 0 or 16
        const float* xi = x + (long)n * 3072;

        // duplicated padded tile: rows h0-1..h0+16, padded cols 0..33
        for (int i = tid; i < 3 * SP2_CH; i += 256) {
            int c = i / SP2_CH, r = i % SP2_CH;
            int yy = r / 34, xx = r % 34;
            int gy = h0 + yy - 1;
            float v = 0.0f;
            if (gy >= 0 && gy < 32 && xx >= 1 && xx < 33)
                v = xi[c * 1024 + gy * 32 + (xx - 1)];
            sp2[i] = pack2(v, v);
        }
        __syncthreads();

        // thread -> row lr (0..15), horizontally adjacent column pair
        const int lr = tid >> 4;
        const int pc0 = (tid & 15) * 2;

        ull acc0[8], acc1[8];
        #pragma unroll
        for (int j = 0; j < 8; j++) { acc0[j] = c_wb[216 + j]; acc1[j] = c_wb[216 + j]; }

        #pragma unroll
        for (int c = 0; c < 3; c++) {
            #pragma unroll
            for (int ky = 0; ky < 3; ky++) {
                const ull* rowp = sp2 + c * SP2_CH + (lr + ky) * 34 + pc0;
                ull v0, v1, v2, v3;
                {
                    ulonglong2 t0 = *reinterpret_cast<const ulonglong2*>(rowp);
                    ulonglong2 t1 = *reinterpret_cast<const ulonglong2*>(rowp + 2);
                    v0 = t0.x; v1 = t0.y; v2 = t1.x; v3 = t1.y;
                }
                #pragma unroll
                for (int kx = 0; kx < 3; kx++) {
                    const ull a = (kx == 0) ? v0 : (kx == 1) ? v1 : v2;
                    const ull b = (kx == 0) ? v1 : (kx == 1) ? v2 : v3;
                    const int tap = (c * 9 + ky * 3 + kx) * 8;
                    #pragma unroll
                    for (int j = 0; j < 8; j++) {
                        const ull w = c_wb[tap + j];
                        acc0[j] = fma2(a, w, acc0[j]);
                        acc1[j] = fma2(b, w, acc1[j]);
                    }
                }
            }
        }

        // epilogue: paired stores + packed stats
        float* yout = y + (long)n * 16 * 1024;
        const int pg = (h0 + lr) * 32 + pc0;
        ull sum2[8], sq2[8];
        #pragma unroll
        for (int j = 0; j < 8; j++) {
            float a0, a1, b0, b1v;
            unpack2(acc0[j], a0, a1);
            unpack2(acc1[j], b0, b1v);
            *reinterpret_cast<float2*>(yout + (2 * j) * 1024 + pg)     = make_float2(a0, b0);
            *reinterpret_cast<float2*>(yout + (2 * j + 1) * 1024 + pg) = make_float2(a1, b1v);
            sum2[j] = add2(acc0[j], acc1[j]);
            sq2[j]  = fma2(acc1[j], acc1[j], fma2(acc0[j], acc0[j], pack2(0.0f, 0.0f)));
        }

        float s[16], q[16];
        #pragma unroll
        for (int j = 0; j < 8; j++) {
            unpack2(sum2[j], s[2 * j], s[2 * j + 1]);
            unpack2(sq2[j],  q[2 * j], q[2 * j + 1]);
        }
        #pragma unroll
        for (int o = 0; o < 16; o++) {
            #pragma unroll
            for (int sft = 16; sft >= 4; sft >>= 1) {
                s[o] += __shfl_down_sync(0xffffffffu, s[o], sft);
                q[o] += __shfl_down_sync(0xffffffffu, q[o], sft);
            }
        }
        const int lane = tid & 31, wp = tid >> 5;
        if (lane < 4) {
            float* rr = red2 + (wp * 4 + lane) * 32;
            #pragma unroll
            for (int o = 0; o < 16; o++) { rr[o] = s[o]; rr[16 + o] = q[o]; }
        }
        __syncthreads();
        if (tid < 32) {
            float t = 0.0f;
            #pragma unroll
            for (int g = 0; g < 32; g++) t += red2[g * 32 + tid];
            g_partials[blockIdx.x * 32 + tid] = t;
        }
        __syncthreads();

        // ---- last-block global stats reduction ----
        if (tid == 0) {
            __threadfence();
            int old = atomicAdd(&g_count, 1);
            *flag = (old == N_CONV_BLOCKS - 1) ? 1 : 0;
        }
        __syncthreads();
        if (*flag) {
            __threadfence();
            const int v = tid & 31, g = tid >> 5;      // 8 groups x 256 blocks
            float t = 0.0f;
            #pragma unroll 8
            for (int b = g * 256; b < (g + 1) * 256; b++)
                t += g_partials[b * 32 + v];
            red2[g * 32 + v] = t;
            __syncthreads();
            if (tid < 32) {
                float tot = 0.0f;
                #pragma unroll
                for (int w = 0; w < 8; w++) tot += red2[w * 32 + tid];
                red2[256 + tid] = tot;
            }
            __syncthreads();
            if (tid < 16) {
                const float inv_n = 1.0f / N_ELEM_PER_CH;
                float mean = red2[256 + tid] * inv_n;
                float var  = red2[256 + 16 + tid] * inv_n - mean * mean;
                float rstd = rsqrtf(var + 1e-5f);
                float sc   = bn_gamma[tid] * rstd;
                g_scale[tid] = sc;
                g_shift[tid] = bn_beta[tid] - mean * sc;
            }
            if (tid == 0) g_count = 0;
        }
    } else {
        // ================= HYPERNET PATH =================
        float* zs = (float*)smem_raw;
        float* hs = zs + 64;
        const int n = blockIdx.x - N_CONV_BLOCKS;

        if (tid < 64) zs[tid] = z_all[n * 64 + tid];
        __syncthreads();

        for (int e = tid; e < 1024; e += 256) {
            float a = b2[e];
            #pragma unroll 16
            for (int k = 0; k < 64; k++)
                a += zs[k] * w2[k * 1024 + e];
            hs[e] = a;
        }
        __syncthreads();

        int li = 0;
        while (c_offs[li + 1] <= n) li++;
        const int r   = n - c_offs[li];
        const int inn = c_in[li];
        const int o   = r / inn;
        const int ii  = r % inn;
        const long base   = (long)c_offs[li] * 2304 + (long)o * inn * 2304 + (long)ii * 144;
        const int  stride = inn * 144;

        const int oo = tid >> 4;
        const int cbase = (tid & 15) * 9;
        float acc[9];
        #pragma unroll
        for (int j = 0; j < 9; j++) acc[j] = b1[cbase + j];
        #pragma unroll 8
        for (int d = 0; d < 64; d++) {
            float hv = hs[oo * 64 + d];
            const float* w1r = w1 + d * 144 + cbase;
            #pragma unroll
            for (int j = 0; j < 9; j++) acc[j] += hv * w1r[j];
        }
        float* op = out + base + (long)oo * stride + cbase;
        #pragma unroll
        for (int j = 0; j < 9; j++) op[j] = acc[j];
    }
}

// ---------------------------------------------------------------------------
// norm: 4 independent float4s per thread (quarter-strided, batched loads) +
// streaming stores (y is write-once, never re-read).
// ---------------------------------------------------------------------------
__global__ __launch_bounds__(256) void norm_kernel(float* __restrict__ y)
{
    __shared__ float sc[16], sh[16];
    if (threadIdx.x < 16) {
        sc[threadIdx.x] = g_scale[threadIdx.x];
        sh[threadIdx.x] = g_shift[threadIdx.x];
    }
    __syncthreads();
    const long qt = (long)16 * 1024 * 1024 / 16;   // 1048576 float4 per quarter
    long i0 = (long)blockIdx.x * blockDim.x + threadIdx.x;
    long i1 = i0 + qt, i2 = i0 + 2 * qt, i3 = i0 + 3 * qt;
    float4* yv = reinterpret_cast<float4*>(y);

    // batch all 4 loads first (MLP=4)
    float4 v0 = yv[i0];
    float4 v1 = yv[i1];
    float4 v2 = yv[i2];
    float4 v3 = yv[i3];

    int c0 = (int)((i0 >> 8) & 15);
    int c1 = (int)((i1 >> 8) & 15);
    int c2 = (int)((i2 >> 8) & 15);
    int c3 = (int)((i3 >> 8) & 15);
    float s0 = sc[c0], b0 = sh[c0];
    float s1 = sc[c1], b1 = sh[c1];
    float s2 = sc[c2], b2 = sh[c2];
    float s3 = sc[c3], b3 = sh[c3];

    v0.x = fmaxf(v0.x * s0 + b0, 0.0f); v0.y = fmaxf(v0.y * s0 + b0, 0.0f);
    v0.z = fmaxf(v0.z * s0 + b0, 0.0f); v0.w = fmaxf(v0.w * s0 + b0, 0.0f);
    v1.x = fmaxf(v1.x * s1 + b1, 0.0f); v1.y = fmaxf(v1.y * s1 + b1, 0.0f);
    v1.z = fmaxf(v1.z * s1 + b1, 0.0f); v1.w = fmaxf(v1.w * s1 + b1, 0.0f);
    v2.x = fmaxf(v2.x * s2 + b2, 0.0f); v2.y = fmaxf(v2.y * s2 + b2, 0.0f);
    v2.z = fmaxf(v2.z * s2 + b2, 0.0f); v2.w = fmaxf(v2.w * s2 + b2, 0.0f);
    v3.x = fmaxf(v3.x * s3 + b3, 0.0f); v3.y = fmaxf(v3.y * s3 + b3, 0.0f);
    v3.z = fmaxf(v3.z * s3 + b3, 0.0f); v3.w = fmaxf(v3.w * s3 + b3, 0.0f);

    __stcs(&yv[i0], v0);
    __stcs(&yv[i1], v1);
    __stcs(&yv[i2], v2);
    __stcs(&yv[i3], v3);
}

// ---------------------------------------------------------------------------
extern "C" void kernel_launch(void* const* d_in, const int* in_sizes, int n_in,
                              void* d_out, int out_size)
{
    const float* x        = (const float*)d_in[0];
    const float* conv_w   = (const float*)d_in[1];
    const float* conv_b   = (const float*)d_in[2];
    const float* bn_gamma = (const float*)d_in[3];
    const float* bn_beta  = (const float*)d_in[4];
    const float* z_all    = (const float*)d_in[5];
    const float* w1       = (const float*)d_in[6];
    const float* b1       = (const float*)d_in[7];
    const float* w2       = (const float*)d_in[8];
    const float* b2       = (const float*)d_in[9];

    float* out = (float*)d_out;
    float* y   = out + Y_OFFSET;

    prep_kernel<<<1, 224>>>(conv_w, conv_b);
    void* stage_addr = nullptr;
    cudaGetSymbolAddress(&stage_addr, g_stage);
    cudaMemcpyToSymbolAsync(c_wb, stage_addr, 224 * sizeof(ull), 0,
                            cudaMemcpyDeviceToDevice, 0);

    fused_conv_hyper<<<N_CONV_BLOCKS + 242, 256>>>(x, y, bn_gamma, bn_beta,
                                                   z_all, w1, b1, w2, b2, out);
    // 4096 blocks x 256 threads x 4 float4 = 16M floats
    norm_kernel<<<4096, 256>>>(y);
}